// round 1
// baseline (speedup 1.0000x reference)
#include <cuda_runtime.h>
#include <math.h>
#include <stdint.h>
#include <stddef.h>

// ---------------------------------------------------------------------------
// TWSABlock: conv(1x1)+BN -> dw3x3+BN -> conv(1x1) +res ; window attention +res ;
//            LN + MLP(GELU) +res.  B=16, C=256, H=W=64, WS=8, NH=4, HD=64.
// Round 1: fp32 baseline. BN folded into conv weights, LN folded into GEMM
// B-operand (per-pixel mu/rstd). One templated SGEMM (64x64 tile, 4x4/thread).
// ---------------------------------------------------------------------------

#define HW 4096
#define NB 16
#define CC 256
#define EPS 1e-5f

// ------------------------------- scratch ----------------------------------
__device__ float g_t1 [NB * CC * HW];        // conv1 out
__device__ float g_t2 [NB * CC * HW];        // dw out
__device__ float g_x1 [NB * CC * HW];        // after conv residual (attn input)
__device__ float g_ob [NB * CC * HW];        // attention output
__device__ float g_x2 [NB * CC * HW];        // after attention residual
__device__ float g_qkv[NB * 3 * CC * HW];    // qkv activations
__device__ float g_hid[NB * 4 * CC * HW];    // mlp hidden
__device__ float g_mu [NB * HW];
__device__ float g_rs [NB * HW];
// folded weights
__device__ float g_w1f [CC * CC];
__device__ float g_b1f [CC];
__device__ float g_dwf [CC * 9];
__device__ float g_dbf [CC];
__device__ float g_qkvf [3 * CC * CC];
__device__ float g_qkvbf[3 * CC];
__device__ float g_m1f [4 * CC * CC];
__device__ float g_m1bf[4 * CC];

// ------------------------------ prep kernel -------------------------------
// Fold BN into conv1/dw weights; fold LN gamma/beta into qkv/mlp1 weights+bias.
__global__ void __launch_bounds__(256) prep_kernel(
    const float* __restrict__ conv1_w, const float* __restrict__ conv1_b,
    const float* __restrict__ bn1_g,  const float* __restrict__ bn1_b,
    const float* __restrict__ bn1_m,  const float* __restrict__ bn1_v,
    const float* __restrict__ dw_w,   const float* __restrict__ dw_b,
    const float* __restrict__ bn2_g,  const float* __restrict__ bn2_b,
    const float* __restrict__ bn2_m,  const float* __restrict__ bn2_v,
    const float* __restrict__ qkv_w,  const float* __restrict__ qkv_b,
    const float* __restrict__ ln1_g,  const float* __restrict__ ln1_b,
    const float* __restrict__ mlp_w1, const float* __restrict__ mlp_b1,
    const float* __restrict__ ln2_g,  const float* __restrict__ ln2_b)
{
    __shared__ float red[8];
    const int r = blockIdx.x;
    const int tid = threadIdx.x;

    if (r < 256) {
        float inv1 = bn1_g[r] * rsqrtf(bn1_v[r] + EPS);
        g_w1f[r * 256 + tid] = conv1_w[r * 256 + tid] * inv1;
        if (tid == 0) g_b1f[r] = conv1_b[r] * inv1 + bn1_b[r] - bn1_m[r] * inv1;
        float inv2 = bn2_g[r] * rsqrtf(bn2_v[r] + EPS);
        if (tid < 9) g_dwf[r * 9 + tid] = dw_w[r * 9 + tid] * inv2;
        if (tid == 0) g_dbf[r] = dw_b[r] * inv2 + bn2_b[r] - bn2_m[r] * inv2;
    }
    if (r < 768) {
        float w = qkv_w[r * 256 + tid];
        g_qkvf[r * 256 + tid] = w * ln1_g[tid];
        float part = w * ln1_b[tid];
        #pragma unroll
        for (int o = 16; o; o >>= 1) part += __shfl_xor_sync(0xffffffffu, part, o);
        if ((tid & 31) == 0) red[tid >> 5] = part;
        __syncthreads();
        if (tid == 0) {
            float s = 0.f;
            #pragma unroll
            for (int w2 = 0; w2 < 8; w2++) s += red[w2];
            g_qkvbf[r] = qkv_b[r] + s;
        }
        __syncthreads();
    }
    if (r < 1024) {
        float w = mlp_w1[r * 256 + tid];
        g_m1f[r * 256 + tid] = w * ln2_g[tid];
        float part = w * ln2_b[tid];
        #pragma unroll
        for (int o = 16; o; o >>= 1) part += __shfl_xor_sync(0xffffffffu, part, o);
        if ((tid & 31) == 0) red[tid >> 5] = part;
        __syncthreads();
        if (tid == 0) {
            float s = 0.f;
            #pragma unroll
            for (int w2 = 0; w2 < 8; w2++) s += red[w2];
            g_m1bf[r] = mlp_b1[r] + s;
        }
    }
}

// ------------------------------- SGEMM ------------------------------------
// out[b, oc, p] = epilog( sum_c A[oc,c] * Bop(b,c,p) + bias[oc] )
// Bop optionally LN-normalized per pixel: (x - mu[g]) * rstd[g].
// Tiles: BM=64 (oc) x BN=64 (pixels) x BK=16. 256 threads, 4x4 per thread.
// EP: 0 = bias only, 1 = bias + residual, 2 = gelu(bias) (exact erf GELU).
template<int KD, bool LN, int EP>
__global__ void __launch_bounds__(256) sgemm_kernel(
    const float* __restrict__ A, const float* __restrict__ B,
    const float* __restrict__ bias,
    const float* __restrict__ mu, const float* __restrict__ rstd,
    const float* __restrict__ res, float* __restrict__ out, int Cout)
{
    __shared__ __align__(16) float As[16][64];
    __shared__ __align__(16) float Bs[16][64];

    const int b   = blockIdx.z;
    const int ocb = blockIdx.y << 6;
    const int pb  = blockIdx.x << 6;
    const int tid = threadIdx.x;

    const int arow = tid >> 2, akq = tid & 3;       // A loader: 64 rows x 4 float4
    const int brow = tid >> 4, bpq = tid & 15;      // B loader: 16 rows x 16 float4
    const int tx   = tid & 15, ty  = tid >> 4;
    const int ty4 = ty << 2, tx4 = tx << 2;

    const float* Aptr = A + (size_t)(ocb + arow) * KD + akq * 4;
    const float* Bptr = B + (size_t)b * KD * HW + (size_t)brow * HW + pb + bpq * 4;

    float4 mu4 = {0, 0, 0, 0}, rs4 = {1, 1, 1, 1};
    if (LN) {
        const int g = (b << 12) + pb + bpq * 4;
        mu4 = *reinterpret_cast<const float4*>(&mu[g]);
        rs4 = *reinterpret_cast<const float4*>(&rstd[g]);
    }

    float acc[4][4];
    #pragma unroll
    for (int i = 0; i < 4; i++)
        #pragma unroll
        for (int j = 0; j < 4; j++) acc[i][j] = 0.f;

    for (int k0 = 0; k0 < KD; k0 += 16) {
        float4 av = *reinterpret_cast<const float4*>(Aptr);
        float4 bv = *reinterpret_cast<const float4*>(Bptr);
        Aptr += 16;
        Bptr += (size_t)16 * HW;
        if (LN) {
            bv.x = (bv.x - mu4.x) * rs4.x;
            bv.y = (bv.y - mu4.y) * rs4.y;
            bv.z = (bv.z - mu4.z) * rs4.z;
            bv.w = (bv.w - mu4.w) * rs4.w;
        }
        As[akq * 4 + 0][arow] = av.x;
        As[akq * 4 + 1][arow] = av.y;
        As[akq * 4 + 2][arow] = av.z;
        As[akq * 4 + 3][arow] = av.w;
        *reinterpret_cast<float4*>(&Bs[brow][bpq * 4]) = bv;
        __syncthreads();

        #pragma unroll
        for (int k = 0; k < 16; ++k) {
            const float4 a4 = *reinterpret_cast<const float4*>(&As[k][ty4]);
            const float4 b4 = *reinterpret_cast<const float4*>(&Bs[k][tx4]);
            float a[4] = {a4.x, a4.y, a4.z, a4.w};
            float bb[4] = {b4.x, b4.y, b4.z, b4.w};
            #pragma unroll
            for (int i = 0; i < 4; i++)
                #pragma unroll
                for (int j = 0; j < 4; j++)
                    acc[i][j] = fmaf(a[i], bb[j], acc[i][j]);
        }
        __syncthreads();
    }

    // epilogue
    #pragma unroll
    for (int i = 0; i < 4; i++) {
        const int oc = ocb + ty4 + i;
        const float bs = bias[oc];
        const size_t ob = ((size_t)b * Cout + oc) * HW + pb + tx4;
        float4 v;
        v.x = acc[i][0] + bs; v.y = acc[i][1] + bs;
        v.z = acc[i][2] + bs; v.w = acc[i][3] + bs;
        if (EP == 2) {  // exact GELU: x * Phi(x)
            v.x = v.x * normcdff(v.x);
            v.y = v.y * normcdff(v.y);
            v.z = v.z * normcdff(v.z);
            v.w = v.w * normcdff(v.w);
        }
        if (EP == 1) {
            const float4 r = *reinterpret_cast<const float4*>(&res[ob]);
            v.x += r.x; v.y += r.y; v.z += r.z; v.w += r.w;
        }
        *reinterpret_cast<float4*>(&out[ob]) = v;
    }
}

// ------------------------------ dw conv 3x3 --------------------------------
__global__ void __launch_bounds__(256) dwconv_kernel(
    const float* __restrict__ in, float* __restrict__ out)
{
    const int plane = blockIdx.x;           // b*256 + c
    const int c = plane & 255;
    const float* ip = in + (size_t)plane * HW;
    float* op = out + (size_t)plane * HW;
    float w[9];
    #pragma unroll
    for (int k = 0; k < 9; k++) w[k] = g_dwf[c * 9 + k];
    const float bias = g_dbf[c];

    for (int idx = threadIdx.x; idx < HW; idx += 256) {
        const int y = idx >> 6, x = idx & 63;
        float acc = bias;
        #pragma unroll
        for (int ky = 0; ky < 3; ky++) {
            const int yy = y + ky - 1;
            if (yy < 0 || yy > 63) continue;
            #pragma unroll
            for (int kx = 0; kx < 3; kx++) {
                const int xx = x + kx - 1;
                if (xx < 0 || xx > 63) continue;
                acc = fmaf(w[ky * 3 + kx], ip[yy * 64 + xx], acc);
            }
        }
        op[idx] = acc;
    }
}

// ------------------------------- LN stats ----------------------------------
__global__ void __launch_bounds__(256) lnstats_kernel(
    const float* __restrict__ x, float* __restrict__ mu, float* __restrict__ rs)
{
    const int g = blockIdx.x * 256 + threadIdx.x;   // 65536 pixels
    const int b = g >> 12, p = g & 4095;
    const float* base = x + (size_t)b * CC * HW + p;
    float s = 0.f, s2 = 0.f;
    #pragma unroll 8
    for (int c = 0; c < CC; c++) {
        const float v = base[(size_t)c * HW];
        s += v;
        s2 = fmaf(v, v, s2);
    }
    const float m = s * (1.f / CC);
    const float var = s2 * (1.f / CC) - m * m;
    mu[g] = m;
    rs[g] = rsqrtf(var + EPS);
}

// ---------------------------- window attention ------------------------------
// One block per (window, head). N=64 tokens, HD=64. 256 threads.
__global__ void __launch_bounds__(256) attn_kernel(
    const float* __restrict__ qkv, float* __restrict__ o)
{
    __shared__ __align__(16) float bufA[64 * 68];
    __shared__ __align__(16) float bufB[64 * 68];

    const int bx = blockIdx.x;
    const int head = bx & 3;
    const int win  = bx >> 2;
    const int b    = win >> 6;
    const int wrem = win & 63;
    const int pbase = (wrem >> 3) * 512 + (wrem & 7) * 8;   // wh*8 rows, ww*8 cols

    const float* qb = qkv + ((size_t)b * 768 + head * 64) * HW;
    const float* kb = qb + (size_t)256 * HW;
    const float* vb = qb + (size_t)512 * HW;

    const int tid = threadIdx.x;
    const int tx = tid & 15, ty = tid >> 4;
    const int ty4 = ty << 2, tx4 = tx << 2;

    // Phase 1: load Q^T, K^T as [d][t], stride 64 (float4-friendly)
    for (int idx = tid; idx < 4096; idx += 256) {
        const int d = idx >> 6, t = idx & 63;
        const int p = pbase + (t >> 3) * 64 + (t & 7);
        bufA[d * 64 + t] = qb[(size_t)d * HW + p];
        bufB[d * 64 + t] = kb[(size_t)d * HW + p];
    }
    __syncthreads();

    // S = Q K^T * scale, 4x4 per thread (rows n = ty4+i, cols m = tx4+j)
    float s[4][4];
    #pragma unroll
    for (int i = 0; i < 4; i++)
        #pragma unroll
        for (int j = 0; j < 4; j++) s[i][j] = 0.f;

    for (int d = 0; d < 64; d++) {
        const float4 q4 = *reinterpret_cast<const float4*>(&bufA[d * 64 + ty4]);
        const float4 k4 = *reinterpret_cast<const float4*>(&bufB[d * 64 + tx4]);
        float q[4] = {q4.x, q4.y, q4.z, q4.w};
        float k[4] = {k4.x, k4.y, k4.z, k4.w};
        #pragma unroll
        for (int i = 0; i < 4; i++)
            #pragma unroll
            for (int j = 0; j < 4; j++)
                s[i][j] = fmaf(q[i], k[j], s[i][j]);
    }

    // softmax over m (spread across the 16 tx-lanes of this ty group)
    const float scale = 0.125f;   // HD^-0.5
    #pragma unroll
    for (int i = 0; i < 4; i++) {
        float mx = -1e30f;
        #pragma unroll
        for (int j = 0; j < 4; j++) { s[i][j] *= scale; mx = fmaxf(mx, s[i][j]); }
        #pragma unroll
        for (int off = 1; off < 16; off <<= 1)
            mx = fmaxf(mx, __shfl_xor_sync(0xffffffffu, mx, off));
        float sum = 0.f;
        #pragma unroll
        for (int j = 0; j < 4; j++) { s[i][j] = __expf(s[i][j] - mx); sum += s[i][j]; }
        #pragma unroll
        for (int off = 1; off < 16; off <<= 1)
            sum += __shfl_xor_sync(0xffffffffu, sum, off);
        const float inv = 1.f / sum;
        #pragma unroll
        for (int j = 0; j < 4; j++) s[i][j] *= inv;
    }
    __syncthreads();   // all done reading Q^T/K^T

    // Phase 2: S -> bufA (stride 68), V[m][d] -> bufB (stride 68)
    #pragma unroll
    for (int i = 0; i < 4; i++)
        #pragma unroll
        for (int j = 0; j < 4; j++)
            bufA[(ty4 + i) * 68 + tx4 + j] = s[i][j];
    for (int idx = tid; idx < 4096; idx += 256) {
        const int d = idx >> 6, m = idx & 63;
        const int p = pbase + (m >> 3) * 64 + (m & 7);
        bufB[m * 68 + d] = vb[(size_t)d * HW + p];
    }
    __syncthreads();

    // O = P V, 4x4 per thread (n = ty4+i, d = tx4+j)
    float oacc[4][4];
    #pragma unroll
    for (int i = 0; i < 4; i++)
        #pragma unroll
        for (int j = 0; j < 4; j++) oacc[i][j] = 0.f;

    for (int m = 0; m < 64; m++) {
        float p4[4];
        #pragma unroll
        for (int i = 0; i < 4; i++) p4[i] = bufA[(ty4 + i) * 68 + m];
        const float4 v4 = *reinterpret_cast<const float4*>(&bufB[m * 68 + tx4]);
        float v[4] = {v4.x, v4.y, v4.z, v4.w};
        #pragma unroll
        for (int i = 0; i < 4; i++)
            #pragma unroll
            for (int j = 0; j < 4; j++)
                oacc[i][j] = fmaf(p4[i], v[j], oacc[i][j]);
    }
    __syncthreads();   // done reading S/V

    // stage O^T [d][t] in bufA (stride 68), then coalesced global write
    #pragma unroll
    for (int i = 0; i < 4; i++)
        #pragma unroll
        for (int j = 0; j < 4; j++)
            bufA[(tx4 + j) * 68 + ty4 + i] = oacc[i][j];
    __syncthreads();

    float* ob = o + ((size_t)b * 256 + head * 64) * HW;
    for (int idx = tid; idx < 4096; idx += 256) {
        const int d = idx >> 6, t = idx & 63;
        const int p = pbase + (t >> 3) * 64 + (t & 7);
        ob[(size_t)d * HW + p] = bufA[d * 68 + t];
    }
}

// ------------------------------- launcher ----------------------------------
extern "C" void kernel_launch(void* const* d_in, const int* in_sizes, int n_in,
                              void* d_out, int out_size)
{
    (void)in_sizes; (void)n_in; (void)out_size;
    const float* x       = (const float*)d_in[0];
    const float* conv1_w = (const float*)d_in[1];
    const float* conv1_b = (const float*)d_in[2];
    const float* bn1_g   = (const float*)d_in[3];
    const float* bn1_b   = (const float*)d_in[4];
    const float* bn1_m   = (const float*)d_in[5];
    const float* bn1_v   = (const float*)d_in[6];
    const float* dw_w    = (const float*)d_in[7];
    const float* dw_b    = (const float*)d_in[8];
    const float* bn2_g   = (const float*)d_in[9];
    const float* bn2_b   = (const float*)d_in[10];
    const float* bn2_m   = (const float*)d_in[11];
    const float* bn2_v   = (const float*)d_in[12];
    const float* conv3_w = (const float*)d_in[13];
    const float* conv3_b = (const float*)d_in[14];
    const float* ln1_g   = (const float*)d_in[15];
    const float* ln1_b   = (const float*)d_in[16];
    const float* qkv_w   = (const float*)d_in[17];
    const float* qkv_b   = (const float*)d_in[18];
    const float* proj_w  = (const float*)d_in[19];
    const float* proj_b  = (const float*)d_in[20];
    const float* ln2_g   = (const float*)d_in[21];
    const float* ln2_b   = (const float*)d_in[22];
    const float* mlp_w1  = (const float*)d_in[23];
    const float* mlp_b1  = (const float*)d_in[24];
    const float* mlp_w2  = (const float*)d_in[25];
    const float* mlp_b2  = (const float*)d_in[26];
    float* out = (float*)d_out;

    float *t1, *t2, *x1, *ob, *x2, *qkvb, *hid, *mu, *rs;
    float *w1f, *b1f, *qkvf, *qkvbf, *m1f, *m1bf;
    cudaGetSymbolAddress((void**)&t1,    g_t1);
    cudaGetSymbolAddress((void**)&t2,    g_t2);
    cudaGetSymbolAddress((void**)&x1,    g_x1);
    cudaGetSymbolAddress((void**)&ob,    g_ob);
    cudaGetSymbolAddress((void**)&x2,    g_x2);
    cudaGetSymbolAddress((void**)&qkvb,  g_qkv);
    cudaGetSymbolAddress((void**)&hid,   g_hid);
    cudaGetSymbolAddress((void**)&mu,    g_mu);
    cudaGetSymbolAddress((void**)&rs,    g_rs);
    cudaGetSymbolAddress((void**)&w1f,   g_w1f);
    cudaGetSymbolAddress((void**)&b1f,   g_b1f);
    cudaGetSymbolAddress((void**)&qkvf,  g_qkvf);
    cudaGetSymbolAddress((void**)&qkvbf, g_qkvbf);
    cudaGetSymbolAddress((void**)&m1f,   g_m1f);
    cudaGetSymbolAddress((void**)&m1bf,  g_m1bf);

    // 0) fold BN/LN into weights
    prep_kernel<<<1024, 256>>>(conv1_w, conv1_b, bn1_g, bn1_b, bn1_m, bn1_v,
                               dw_w, dw_b, bn2_g, bn2_b, bn2_m, bn2_v,
                               qkv_w, qkv_b, ln1_g, ln1_b,
                               mlp_w1, mlp_b1, ln2_g, ln2_b);

    const dim3 gConv(64, 4, 16);    // Cout=256
    const dim3 gQkv (64, 12, 16);   // Cout=768
    const dim3 gMlp1(64, 16, 16);   // Cout=1024

    // 1) conv1 + BN1 (folded)
    sgemm_kernel<256, false, 0><<<gConv, 256>>>(w1f, x, b1f, nullptr, nullptr,
                                                nullptr, t1, 256);
    // 2) dw 3x3 + BN2 (folded)
    dwconv_kernel<<<NB * CC, 256>>>(t1, t2);
    // 3) conv3 + residual(x)
    sgemm_kernel<256, false, 1><<<gConv, 256>>>(conv3_w, t2, conv3_b, nullptr,
                                                nullptr, x, x1, 256);
    // 4) LN1 stats
    lnstats_kernel<<<256, 256>>>(x1, mu, rs);
    // 5) QKV gemm (LN fused)
    sgemm_kernel<256, true, 0><<<gQkv, 256>>>(qkvf, x1, qkvbf, mu, rs,
                                              nullptr, qkvb, 768);
    // 6) window attention
    attn_kernel<<<4096, 256>>>(qkvb, ob);
    // 7) proj + residual(x1)
    sgemm_kernel<256, false, 1><<<gConv, 256>>>(proj_w, ob, proj_b, nullptr,
                                                nullptr, x1, x2, 256);
    // 8) LN2 stats
    lnstats_kernel<<<256, 256>>>(x2, mu, rs);
    // 9) MLP1 (LN fused) + GELU
    sgemm_kernel<256, true, 2><<<gMlp1, 256>>>(m1f, x2, m1bf, mu, rs,
                                               nullptr, hid, 1024);
    // 10) MLP2 + residual(x2) -> out
    sgemm_kernel<1024, false, 1><<<gConv, 256>>>(mlp_w2, hid, mlp_b2, nullptr,
                                                 nullptr, x2, out, 256);
}